// round 15
// baseline (speedup 1.0000x reference)
#include <cuda_runtime.h>
#include <stdint.h>

typedef unsigned long long ull;

#define NMAX   100000
#define EMAX   1600000
#define DIN    128
#define DOUT   32
#define CAP    64        // per-node source bucket capacity (deg ~ Poisson(16))
#define BM     128
#define BK     32

// ---- scratch (no allocations allowed) ----
__device__ float g_h[NMAX * DOUT];        // raw x@W from gemm; scaled in-place by k_scale
__device__ float g_dinv[NMAX];            // (deg)^{-1/2}, deg = in-edges + 1
__device__ int   g_fill[NMAX + 1];        // [0..NMAX): in-degree; [NMAX]: ovf count
__device__ int   g_srcs[NMAX * CAP];      // bucketed sources per dst (zero-init; only valid ids ever written)
__device__ int   g_ovf[2 * EMAX];         // overflow (src,dst) pairs

__device__ __forceinline__ ull pack_dup(float a) {
    ull r;
    asm("mov.b64 %0, {%1, %1};" : "=l"(r) : "f"(a));
    return r;
}
__device__ __forceinline__ void fma2(ull& acc, ull a, ull b) {
    asm("fma.rn.f32x2 %0, %1, %2, %0;" : "+l"(acc) : "l"(a), "l"(b));
}
__device__ __forceinline__ float2 unpack2(ull v) {
    float lo, hi;
    asm("mov.b64 {%0, %1}, %2;" : "=f"(lo), "=f"(hi) : "l"(v));
    return make_float2(lo, hi);
}

// ---------------------------------------------------------------------------
// Bucket placement (binder is L2-side atomic service; 1 edge/thread proven
// best in R8 vs R10). Dtype detection per block: int64 (LE, values < 2^31)
// => all odd 32-bit words zero; 256 random int32 samples all-zero ~1e-1280.
// ---------------------------------------------------------------------------
__global__ void k_place(const void* __restrict__ ei, int E) {
    __shared__ int s_is64;
    if (threadIdx.x == 0) s_is64 = 1;
    __syncthreads();
    if (((const unsigned*)ei)[2 * threadIdx.x + 1] != 0u) s_is64 = 0;
    __syncthreads();
    int is64 = s_is64;

    int e = blockIdx.x * blockDim.x + threadIdx.x;
    if (e >= E) return;
    int src, dst;
    if (is64) {
        src = (int)((const long long*)ei)[e];
        dst = (int)((const long long*)ei)[(long long)E + e];
    } else {
        src = ((const int*)ei)[e];
        dst = ((const int*)ei)[E + e];
    }
    int pos = atomicAdd(&g_fill[dst], 1);
    if (pos < CAP) {
        g_srcs[dst * CAP + pos] = src;
    } else {
        int o = atomicAdd(&g_fill[NMAX], 1);
        if (o < EMAX) { g_ovf[2 * o] = src; g_ovf[2 * o + 1] = dst; }
    }
}

// ---------------------------------------------------------------------------
// GEMM mainloop, FFMA2 paired across column pairs (R14-proven, bit-exact
// per-element chains, same registers/occupancy as scalar). Writes RAW acc.
// ---------------------------------------------------------------------------
__global__ void k_gemm(const float* __restrict__ x, const float* __restrict__ W,
                       int n) {
    __shared__ float xs[BM][BK + 1];   // 16.5 KB
    __shared__ float ws[BK][DOUT];     // 4 KB
    int t = threadIdx.x;
    int row0 = blockIdx.x * BM;
    int tx = t & 7, ty = t >> 3;

    ull acc2[4][2];
#pragma unroll
    for (int i = 0; i < 4; i++) { acc2[i][0] = 0ull; acc2[i][1] = 0ull; }

    for (int kc = 0; kc < DIN; kc += BK) {
#pragma unroll
        for (int it = 0; it < 4; it++) {
            int i = t + it * 256;
            int r = i >> 3, k4 = i & 7;
            int gr = row0 + r;
            float4 v = make_float4(0.f, 0.f, 0.f, 0.f);
            if (gr < n)
                v = __ldcs((const float4*)&x[(size_t)gr * DIN + kc + k4 * 4]);
            xs[r][k4 * 4 + 0] = v.x;
            xs[r][k4 * 4 + 1] = v.y;
            xs[r][k4 * 4 + 2] = v.z;
            xs[r][k4 * 4 + 3] = v.w;
        }
        ((float4*)ws)[t] = ((const float4*)(W + kc * DOUT))[t];
        __syncthreads();

#pragma unroll
        for (int k = 0; k < BK; k++) {
            float a0 = xs[ty * 4 + 0][k];
            float a1 = xs[ty * 4 + 1][k];
            float a2 = xs[ty * 4 + 2][k];
            float a3 = xs[ty * 4 + 3][k];
            ulonglong2 w = *(const ulonglong2*)&ws[k][tx * 4];  // {c0,c1},{c2,c3}
            ull p0 = pack_dup(a0), p1 = pack_dup(a1);
            ull p2 = pack_dup(a2), p3 = pack_dup(a3);
            fma2(acc2[0][0], p0, w.x); fma2(acc2[0][1], p0, w.y);
            fma2(acc2[1][0], p1, w.x); fma2(acc2[1][1], p1, w.y);
            fma2(acc2[2][0], p2, w.x); fma2(acc2[2][1], p2, w.y);
            fma2(acc2[3][0], p3, w.x); fma2(acc2[3][1], p3, w.y);
        }
        __syncthreads();
    }

#pragma unroll
    for (int i = 0; i < 4; i++) {
        int row = row0 + ty * 4 + i;
        if (row >= n) break;
        float2 lo = unpack2(acc2[i][0]);
        float2 hi = unpack2(acc2[i][1]);
        float4 o = make_float4(lo.x, lo.y, hi.x, hi.y);
        *(float4*)&g_h[row * DOUT + tx * 4] = o;
    }
}

// ---------------------------------------------------------------------------
// Join epilogue (slimmed): dinv = rsqrt(1+deg); g_h *= dinv.
// out is written here ONLY for overflow nodes (fill > CAP, normally none),
// so that k_agg's and the cleanup's atomicAdds land on initialized data.
// Normal nodes get out written (store-only) by k_agg.
// ---------------------------------------------------------------------------
__global__ void k_scale(const float* __restrict__ b, float* __restrict__ out, int n) {
    int tid = blockIdx.x * 256 + threadIdx.x;
    int row = tid >> 3, c4 = tid & 7;
    if (row >= n) return;
    int fill = g_fill[row];
    float dinv = rsqrtf(1.0f + (float)fill);
    if (c4 == 0) g_dinv[row] = dinv;
    float4 a = *(float4*)&g_h[row * DOUT + c4 * 4];
    float4 hs = make_float4(a.x * dinv, a.y * dinv, a.z * dinv, a.w * dinv);
    *(float4*)&g_h[row * DOUT + c4 * 4] = hs;
    if (fill > CAP) {   // cold path: init out with self-loop + bias
        float4 bb = *(const float4*)&b[c4 * 4];
        float4 o;
        o.x = fmaf(hs.x, dinv, bb.x);
        o.y = fmaf(hs.y, dinv, bb.y);
        o.z = fmaf(hs.z, dinv, bb.z);
        o.w = fmaf(hs.w, dinv, bb.w);
        *(float4*)&out[row * DOUT + c4 * 4] = o;
    }
}

// ---------------------------------------------------------------------------
// Pull-side aggregation, store-only out:
//   out[d] = dd * (hself_scaled + sum_s hscaled[s]) + b
// Front batch (all parallel, addresses depend only on d): 16 srcs, cnt, dd,
// hself row, bias. No index clamp: g_srcs is zero-init device memory and
// only ever written with valid ids < n, so every slot is in-bounds.
// Overflow nodes (fill > CAP): self-term was written by k_scale; agg and the
// cleanup blocks contribute via atomicAdd (commutative).
// ---------------------------------------------------------------------------
__global__ void __launch_bounds__(128) k_agg(const float* __restrict__ b,
                                             float* __restrict__ out, int n, int nb_agg) {
    if (blockIdx.x >= nb_agg) {
        int cnt = g_fill[NMAX];
        if (cnt > EMAX) cnt = EMAX;
        int tid = (blockIdx.x - nb_agg) * 128 + threadIdx.x;
        for (int o = tid; o < cnt; o += 16 * 128) {
            int src = g_ovf[2 * o], dst = g_ovf[2 * o + 1];
            float nrm = g_dinv[dst];
            for (int c = 0; c < DOUT; c++)
                atomicAdd(&out[dst * DOUT + c], g_h[src * DOUT + c] * nrm);
        }
        return;
    }

    int warp = threadIdx.x >> 5, lane = threadIdx.x & 31;
    int d = blockIdx.x * 4 + warp;
    if (d >= n) return;

    int q  = lane >> 3;
    int c4 = lane & 7;

    const int* sr = &g_srcs[d * CAP];

    // parallel front batch (addresses depend only on d)
    int s0 = sr[q];
    int s1 = sr[4 + q];
    int s2 = sr[8 + q];
    int s3 = sr[12 + q];
    int cnt_raw = g_fill[d];
    float dd = g_dinv[d];
    float4 hself = *(const float4*)&g_h[d * DOUT + c4 * 4];
    float4 bb = *(const float4*)&b[c4 * 4];

    float4 h0 = *(const float4*)&g_h[s0 * DOUT + c4 * 4];
    float4 h1 = *(const float4*)&g_h[s1 * DOUT + c4 * 4];
    float4 h2 = *(const float4*)&g_h[s2 * DOUT + c4 * 4];
    float4 h3 = *(const float4*)&g_h[s3 * DOUT + c4 * 4];

    int cnt = cnt_raw > CAP ? CAP : cnt_raw;

    float4 a0 = make_float4(0.f, 0.f, 0.f, 0.f);
    float4 a1 = make_float4(0.f, 0.f, 0.f, 0.f);
    if (q      < cnt) { a0.x += h0.x; a0.y += h0.y; a0.z += h0.z; a0.w += h0.w; }
    if (4 + q  < cnt) { a1.x += h1.x; a1.y += h1.y; a1.z += h1.z; a1.w += h1.w; }
    if (8 + q  < cnt) { a0.x += h2.x; a0.y += h2.y; a0.z += h2.z; a0.w += h2.w; }
    if (12 + q < cnt) { a1.x += h3.x; a1.y += h3.y; a1.z += h3.z; a1.w += h3.w; }

    for (int j = 16; j < cnt; j += 8) {
        int t0 = sr[j + q];              // j+q .. j+7+q <= 63 < CAP always
        int t1 = sr[j + 4 + q];
        float4 g0 = *(const float4*)&g_h[t0 * DOUT + c4 * 4];
        float4 g1 = *(const float4*)&g_h[t1 * DOUT + c4 * 4];
        if (j + q     < cnt) { a0.x += g0.x; a0.y += g0.y; a0.z += g0.z; a0.w += g0.w; }
        if (j + 4 + q < cnt) { a1.x += g1.x; a1.y += g1.y; a1.z += g1.z; a1.w += g1.w; }
    }

    a0.x += a1.x; a0.y += a1.y; a0.z += a1.z; a0.w += a1.w;

    // reduce quarters (lane bits 3,4)
    a0.x += __shfl_xor_sync(0xffffffffu, a0.x, 8);
    a0.y += __shfl_xor_sync(0xffffffffu, a0.y, 8);
    a0.z += __shfl_xor_sync(0xffffffffu, a0.z, 8);
    a0.w += __shfl_xor_sync(0xffffffffu, a0.w, 8);
    a0.x += __shfl_xor_sync(0xffffffffu, a0.x, 16);
    a0.y += __shfl_xor_sync(0xffffffffu, a0.y, 16);
    a0.z += __shfl_xor_sync(0xffffffffu, a0.z, 16);
    a0.w += __shfl_xor_sync(0xffffffffu, a0.w, 16);

    if (lane < 8) {
        if (cnt_raw <= CAP) {
            // store-only: out = dd*(hself + sum) + b
            float4 o;
            o.x = fmaf(hself.x + a0.x, dd, bb.x);
            o.y = fmaf(hself.y + a0.y, dd, bb.y);
            o.z = fmaf(hself.z + a0.z, dd, bb.z);
            o.w = fmaf(hself.w + a0.w, dd, bb.w);
            *(float4*)&out[d * DOUT + c4 * 4] = o;
        } else {
            // overflow node: self+bias initialized by k_scale; add our part
            float* os = &out[d * DOUT + c4 * 4];
            atomicAdd(os + 0, a0.x * dd);
            atomicAdd(os + 1, a0.y * dd);
            atomicAdd(os + 2, a0.z * dd);
            atomicAdd(os + 3, a0.w * dd);
        }
    }
}

// ---------------------------------------------------------------------------
// Launch graph:
//   s0: memset(fill) -> k_place ─┐
//   s2 (high prio): k_gemm      ─┴─ join -> k_scale -> k_agg
// Stream/events created lazily on the FIRST (uncaptured) call only.
// ---------------------------------------------------------------------------
extern "C" void kernel_launch(void* const* d_in, const int* in_sizes, int n_in,
                              void* d_out, int out_size) {
    const float* x  = (const float*)d_in[0];
    const void*  ei = d_in[1];
    const float* W  = (const float*)d_in[2];
    const float* b  = (const float*)d_in[3];
    float* out = (float*)d_out;

    int n = in_sizes[0] / DIN;   // 100000
    int E = in_sizes[1] / 2;     // 1600000

    static cudaStream_t s2 = nullptr;
    static cudaEvent_t evFork = nullptr, evJoin = nullptr;
    if (!s2) {
        int loPrio, hiPrio;
        cudaDeviceGetStreamPriorityRange(&loPrio, &hiPrio);
        cudaStreamCreateWithPriority(&s2, cudaStreamNonBlocking, hiPrio);
        cudaEventCreateWithFlags(&evFork, cudaEventDisableTiming);
        cudaEventCreateWithFlags(&evJoin, cudaEventDisableTiming);
    }

    void* fill_ptr = nullptr;
    cudaGetSymbolAddress(&fill_ptr, g_fill);

    // fork: gemm branch on s2 (touches only x, W, g_h)
    cudaEventRecord(evFork, 0);
    cudaStreamWaitEvent(s2, evFork, 0);
    k_gemm<<<(n + BM - 1) / BM, 256, 0, s2>>>(x, W, n);
    cudaEventRecord(evJoin, s2);

    // place branch on stream 0
    cudaMemsetAsync(fill_ptr, 0, (NMAX + 1) * sizeof(int), 0);
    k_place<<<(E + 255) / 256, 256>>>(ei, E);

    // join, then epilogue + aggregation
    cudaStreamWaitEvent(0, evJoin, 0);
    k_scale<<<(n * 8 + 255) / 256, 256>>>(b, out, n);

    int nb_agg = (n + 3) / 4;
    k_agg<<<nb_agg + 16, 128>>>(b, out, n, nb_agg);
}

// round 16
// speedup vs baseline: 1.0241x; 1.0241x over previous
#include <cuda_runtime.h>
#include <stdint.h>

typedef unsigned long long ull;

#define NMAX   100000
#define EMAX   1600000
#define DIN    128
#define DOUT   32
#define CAP    64        // per-node source bucket capacity (deg ~ Poisson(16))
#define BM     128
#define BK     32

// ---- scratch (no allocations allowed) ----
__device__ float g_h[NMAX * DOUT];        // raw x@W, scaled in-place by k_scale
__device__ float g_dinv[NMAX];            // (deg)^{-1/2}, deg = in-edges + 1
__device__ int   g_fill[NMAX + 1];        // [0..NMAX): in-degree; [NMAX]: ovf count
__device__ int   g_srcs[NMAX * CAP];      // bucketed sources per dst (zero-init; only valid ids < n ever written)
__device__ int   g_ovf[2 * EMAX];         // overflow (src,dst) pairs

__device__ __forceinline__ ull pack_dup(float a) {
    ull r;
    asm("mov.b64 %0, {%1, %1};" : "=l"(r) : "f"(a));
    return r;
}
__device__ __forceinline__ void fma2(ull& acc, ull a, ull b) {
    asm("fma.rn.f32x2 %0, %1, %2, %0;" : "+l"(acc) : "l"(a), "l"(b));
}
__device__ __forceinline__ float2 unpack2(ull v) {
    float lo, hi;
    asm("mov.b64 {%0, %1}, %2;" : "=f"(lo), "=f"(hi) : "l"(v));
    return make_float2(lo, hi);
}

// ---------------------------------------------------------------------------
// Bucket placement (binder is L2-side atomic service; 1 edge/thread proven
// best in R8 vs R10). Dtype detection per block: int64 (LE, values < 2^31)
// => all odd 32-bit words zero; 256 random int32 samples all-zero ~1e-1280.
// ---------------------------------------------------------------------------
__global__ void k_place(const void* __restrict__ ei, int E) {
    __shared__ int s_is64;
    if (threadIdx.x == 0) s_is64 = 1;
    __syncthreads();
    if (((const unsigned*)ei)[2 * threadIdx.x + 1] != 0u) s_is64 = 0;
    __syncthreads();
    int is64 = s_is64;

    int e = blockIdx.x * blockDim.x + threadIdx.x;
    if (e >= E) return;
    int src, dst;
    if (is64) {
        src = (int)((const long long*)ei)[e];
        dst = (int)((const long long*)ei)[(long long)E + e];
    } else {
        src = ((const int*)ei)[e];
        dst = ((const int*)ei)[E + e];
    }
    int pos = atomicAdd(&g_fill[dst], 1);
    if (pos < CAP) {
        g_srcs[dst * CAP + pos] = src;
    } else {
        int o = atomicAdd(&g_fill[NMAX], 1);
        if (o < EMAX) { g_ovf[2 * o] = src; g_ovf[2 * o + 1] = dst; }
    }
}

// ---------------------------------------------------------------------------
// GEMM mainloop, FFMA2 paired across column pairs (R14-proven, bit-exact
// per-element chains, same registers/occupancy as scalar). Writes RAW acc.
// ---------------------------------------------------------------------------
__global__ void k_gemm(const float* __restrict__ x, const float* __restrict__ W,
                       int n) {
    __shared__ float xs[BM][BK + 1];   // 16.5 KB
    __shared__ float ws[BK][DOUT];     // 4 KB
    int t = threadIdx.x;
    int row0 = blockIdx.x * BM;
    int tx = t & 7, ty = t >> 3;

    ull acc2[4][2];
#pragma unroll
    for (int i = 0; i < 4; i++) { acc2[i][0] = 0ull; acc2[i][1] = 0ull; }

    for (int kc = 0; kc < DIN; kc += BK) {
#pragma unroll
        for (int it = 0; it < 4; it++) {
            int i = t + it * 256;
            int r = i >> 3, k4 = i & 7;
            int gr = row0 + r;
            float4 v = make_float4(0.f, 0.f, 0.f, 0.f);
            if (gr < n)
                v = __ldcs((const float4*)&x[(size_t)gr * DIN + kc + k4 * 4]);
            xs[r][k4 * 4 + 0] = v.x;
            xs[r][k4 * 4 + 1] = v.y;
            xs[r][k4 * 4 + 2] = v.z;
            xs[r][k4 * 4 + 3] = v.w;
        }
        ((float4*)ws)[t] = ((const float4*)(W + kc * DOUT))[t];
        __syncthreads();

#pragma unroll
        for (int k = 0; k < BK; k++) {
            float a0 = xs[ty * 4 + 0][k];
            float a1 = xs[ty * 4 + 1][k];
            float a2 = xs[ty * 4 + 2][k];
            float a3 = xs[ty * 4 + 3][k];
            ulonglong2 w = *(const ulonglong2*)&ws[k][tx * 4];  // {c0,c1},{c2,c3}
            ull p0 = pack_dup(a0), p1 = pack_dup(a1);
            ull p2 = pack_dup(a2), p3 = pack_dup(a3);
            fma2(acc2[0][0], p0, w.x); fma2(acc2[0][1], p0, w.y);
            fma2(acc2[1][0], p1, w.x); fma2(acc2[1][1], p1, w.y);
            fma2(acc2[2][0], p2, w.x); fma2(acc2[2][1], p2, w.y);
            fma2(acc2[3][0], p3, w.x); fma2(acc2[3][1], p3, w.y);
        }
        __syncthreads();
    }

#pragma unroll
    for (int i = 0; i < 4; i++) {
        int row = row0 + ty * 4 + i;
        if (row >= n) break;
        float2 lo = unpack2(acc2[i][0]);
        float2 hi = unpack2(acc2[i][1]);
        float4 o = make_float4(lo.x, lo.y, hi.x, hi.y);
        *(float4*)&g_h[row * DOUT + tx * 4] = o;
    }
}

// ---------------------------------------------------------------------------
// Join epilogue (R14-proven): dinv = rsqrt(1+deg); g_h *= dinv;
// out = g_h*dinv + b (self-loop + bias).
// ---------------------------------------------------------------------------
__global__ void k_scale(const float* __restrict__ b, float* __restrict__ out, int n) {
    int tid = blockIdx.x * 256 + threadIdx.x;
    int row = tid >> 3, c4 = tid & 7;
    if (row >= n) return;
    float dinv = rsqrtf(1.0f + (float)g_fill[row]);
    if (c4 == 0) g_dinv[row] = dinv;
    float4 a = *(float4*)&g_h[row * DOUT + c4 * 4];
    float4 hs = make_float4(a.x * dinv, a.y * dinv, a.z * dinv, a.w * dinv);
    *(float4*)&g_h[row * DOUT + c4 * 4] = hs;
    float4 bb = *(const float4*)&b[c4 * 4];
    float4 o;
    o.x = fmaf(hs.x, dinv, bb.x);
    o.y = fmaf(hs.y, dinv, bb.y);
    o.z = fmaf(hs.z, dinv, bb.z);
    o.w = fmaf(hs.w, dinv, bb.w);
    *(float4*)&out[row * DOUT + c4 * 4] = o;
}

// ---------------------------------------------------------------------------
// Pull-side aggregation (R14 structure; ONLY change: index clamp removed —
// g_srcs is zero-init and only ever holds valid ids < n, so speculative
// reads of slots >= cnt are in-bounds by construction).
// ---------------------------------------------------------------------------
__global__ void __launch_bounds__(128) k_agg(float* __restrict__ out, int n, int nb_agg) {
    if (blockIdx.x >= nb_agg) {
        int cnt = g_fill[NMAX];
        if (cnt > EMAX) cnt = EMAX;
        int tid = (blockIdx.x - nb_agg) * 128 + threadIdx.x;
        for (int o = tid; o < cnt; o += 16 * 128) {
            int src = g_ovf[2 * o], dst = g_ovf[2 * o + 1];
            float nrm = g_dinv[dst];
            for (int c = 0; c < DOUT; c++)
                atomicAdd(&out[dst * DOUT + c], g_h[src * DOUT + c] * nrm);
        }
        return;
    }

    int warp = threadIdx.x >> 5, lane = threadIdx.x & 31;
    int d = blockIdx.x * 4 + warp;
    if (d >= n) return;

    int q  = lane >> 3;
    int c4 = lane & 7;

    const int* sr = &g_srcs[d * CAP];

    // parallel front batch (addresses depend only on d)
    int s0 = sr[q];
    int s1 = sr[4 + q];
    int s2 = sr[8 + q];
    int s3 = sr[12 + q];
    int cnt_raw = g_fill[d];
    float dd = g_dinv[d];
    float4* op = (float4*)&out[d * DOUT + c4 * 4];
    float4 oval = *op;

    float4 h0 = *(const float4*)&g_h[s0 * DOUT + c4 * 4];
    float4 h1 = *(const float4*)&g_h[s1 * DOUT + c4 * 4];
    float4 h2 = *(const float4*)&g_h[s2 * DOUT + c4 * 4];
    float4 h3 = *(const float4*)&g_h[s3 * DOUT + c4 * 4];

    int cnt = cnt_raw > CAP ? CAP : cnt_raw;

    float4 a0 = make_float4(0.f, 0.f, 0.f, 0.f);
    float4 a1 = make_float4(0.f, 0.f, 0.f, 0.f);
    if (q      < cnt) { a0.x += h0.x; a0.y += h0.y; a0.z += h0.z; a0.w += h0.w; }
    if (4 + q  < cnt) { a1.x += h1.x; a1.y += h1.y; a1.z += h1.z; a1.w += h1.w; }
    if (8 + q  < cnt) { a0.x += h2.x; a0.y += h2.y; a0.z += h2.z; a0.w += h2.w; }
    if (12 + q < cnt) { a1.x += h3.x; a1.y += h3.y; a1.z += h3.z; a1.w += h3.w; }

    for (int j = 16; j < cnt; j += 8) {
        int t0 = sr[j + q];              // j+q .. j+7+q <= 63 < CAP always
        int t1 = sr[j + 4 + q];
        float4 g0 = *(const float4*)&g_h[t0 * DOUT + c4 * 4];
        float4 g1 = *(const float4*)&g_h[t1 * DOUT + c4 * 4];
        if (j + q     < cnt) { a0.x += g0.x; a0.y += g0.y; a0.z += g0.z; a0.w += g0.w; }
        if (j + 4 + q < cnt) { a1.x += g1.x; a1.y += g1.y; a1.z += g1.z; a1.w += g1.w; }
    }

    a0.x += a1.x; a0.y += a1.y; a0.z += a1.z; a0.w += a1.w;

    // reduce quarters (lane bits 3,4)
    a0.x += __shfl_xor_sync(0xffffffffu, a0.x, 8);
    a0.y += __shfl_xor_sync(0xffffffffu, a0.y, 8);
    a0.z += __shfl_xor_sync(0xffffffffu, a0.z, 8);
    a0.w += __shfl_xor_sync(0xffffffffu, a0.w, 8);
    a0.x += __shfl_xor_sync(0xffffffffu, a0.x, 16);
    a0.y += __shfl_xor_sync(0xffffffffu, a0.y, 16);
    a0.z += __shfl_xor_sync(0xffffffffu, a0.z, 16);
    a0.w += __shfl_xor_sync(0xffffffffu, a0.w, 16);

    if (lane < 8) {
        if (cnt_raw <= CAP) {
            oval.x = fmaf(a0.x, dd, oval.x);
            oval.y = fmaf(a0.y, dd, oval.y);
            oval.z = fmaf(a0.z, dd, oval.z);
            oval.w = fmaf(a0.w, dd, oval.w);
            *op = oval;
        } else {
            float* os = (float*)op;
            atomicAdd(os + 0, a0.x * dd);
            atomicAdd(os + 1, a0.y * dd);
            atomicAdd(os + 2, a0.z * dd);
            atomicAdd(os + 3, a0.w * dd);
        }
    }
}

// ---------------------------------------------------------------------------
// Launch graph (R14-proven):
//   s0: memset(fill) -> k_place ─┐
//   s2: k_gemm (independent)    ─┴─ join -> k_scale -> k_agg
// Stream/events created lazily on the FIRST (uncaptured) call only.
// ---------------------------------------------------------------------------
extern "C" void kernel_launch(void* const* d_in, const int* in_sizes, int n_in,
                              void* d_out, int out_size) {
    const float* x  = (const float*)d_in[0];
    const void*  ei = d_in[1];
    const float* W  = (const float*)d_in[2];
    const float* b  = (const float*)d_in[3];
    float* out = (float*)d_out;

    int n = in_sizes[0] / DIN;   // 100000
    int E = in_sizes[1] / 2;     // 1600000

    static cudaStream_t s2 = nullptr;
    static cudaEvent_t evFork = nullptr, evJoin = nullptr;
    if (!s2) {
        cudaStreamCreateWithFlags(&s2, cudaStreamNonBlocking);
        cudaEventCreateWithFlags(&evFork, cudaEventDisableTiming);
        cudaEventCreateWithFlags(&evJoin, cudaEventDisableTiming);
    }

    void* fill_ptr = nullptr;
    cudaGetSymbolAddress(&fill_ptr, g_fill);

    // fork: gemm branch on s2 (touches only x, W, g_h)
    cudaEventRecord(evFork, 0);
    cudaStreamWaitEvent(s2, evFork, 0);
    k_gemm<<<(n + BM - 1) / BM, 256, 0, s2>>>(x, W, n);
    cudaEventRecord(evJoin, s2);

    // place branch on stream 0
    cudaMemsetAsync(fill_ptr, 0, (NMAX + 1) * sizeof(int), 0);
    k_place<<<(E + 255) / 256, 256>>>(ei, E);

    // join, then epilogue + aggregation
    cudaStreamWaitEvent(0, evJoin, 0);
    k_scale<<<(n * 8 + 255) / 256, 256>>>(b, out, n);

    int nb_agg = (n + 3) / 4;
    k_agg<<<nb_agg + 16, 128>>>(out, n, nb_agg);
}